// round 1
// baseline (speedup 1.0000x reference)
#include <cuda_runtime.h>
#include <cstdint>

#define VOCAB 14
#define EMBED 10
#define HID   50
#define HP    64          // padded units
#define TLEN  2048
#define NBATCH 4096

typedef unsigned long long ull;

// Precomputed tables (global memory; L1-resident during main loop)
__device__ float4 gWk[HID * HP];     // [k][u] -> (Wi, Wf, Wg, Wo) = W_hh[g*50+u][k]
__device__ float4 gXT[VOCAB * HP];   // [v][u] -> per-token gate init (x@W_ih.T + b_ih + b_hh)
__device__ float  gq[HID];           // collapsed head: q = W2 @ W1
__device__ float  gc0;               // collapsed head bias: b2 + W2 @ b1

// ---------------------------------------------------------------------------
// Prep kernel: build gate-init table, regathered W_hh, collapsed head.
// ---------------------------------------------------------------------------
__global__ void prep_kernel(const float* __restrict__ emb,
                            const float* __restrict__ W_ih,
                            const float* __restrict__ W_hh,
                            const float* __restrict__ b_ih,
                            const float* __restrict__ b_hh,
                            const float* __restrict__ W1,
                            const float* __restrict__ b1,
                            const float* __restrict__ W2,
                            const float* __restrict__ b2)
{
    int tid = threadIdx.x;

    for (int i = tid; i < HID * HP; i += blockDim.x) {
        int k = i / HP, u = i % HP;
        float4 w = make_float4(0.f, 0.f, 0.f, 0.f);
        if (u < HID) {
            w.x = W_hh[(0 * HID + u) * HID + k];
            w.y = W_hh[(1 * HID + u) * HID + k];
            w.z = W_hh[(2 * HID + u) * HID + k];
            w.w = W_hh[(3 * HID + u) * HID + k];
        }
        gWk[i] = w;
    }

    for (int i = tid; i < VOCAB * HP; i += blockDim.x) {
        int v = i / HP, u = i % HP;
        float4 x = make_float4(0.f, 0.f, 0.f, 0.f);
        if (u < HID) {
            float* px = reinterpret_cast<float*>(&x);
            #pragma unroll
            for (int g = 0; g < 4; g++) {
                int c = g * HID + u;
                float s = b_ih[c] + b_hh[c];
                #pragma unroll
                for (int e = 0; e < EMBED; e++)
                    s += emb[v * EMBED + e] * W_ih[c * EMBED + e];
                px[g] = s;
            }
        }
        gXT[i] = x;
    }

    for (int u = tid; u < HID; u += blockDim.x) {
        float s = 0.f;
        for (int m = 0; m < HID; m++) s += W2[m] * W1[m * HID + u];
        gq[u] = s;
    }
    if (tid == 0) {
        float s = b2[0];
        for (int m = 0; m < HID; m++) s += W2[m] * b1[m];
        gc0 = s;
    }
}

// ---------------------------------------------------------------------------
// Main LSTM kernel: 1 warp = 8 batch rows, fully warp-autonomous recurrence.
// Lane L owns units {L, L+32}; f32x2 packs (i,f) and (g,o) gate pairs;
// h is stored duplicated (h,h) in SMEM so the FFMA2 splat is one LDS.64.
// ---------------------------------------------------------------------------
__device__ __forceinline__ ull ffma2(ull a, ull b, ull c) {
    ull d;
    asm("fma.rn.f32x2 %0, %1, %2, %3;" : "=l"(d) : "l"(a), "l"(b), "l"(c));
    return d;
}
__device__ __forceinline__ ull pk2(float x, float y) {
    ull d;
    asm("mov.b64 %0, {%1, %2};" : "=l"(d) : "f"(x), "f"(y));
    return d;
}
__device__ __forceinline__ float lo_(ull v) { return __uint_as_float((unsigned)v); }
__device__ __forceinline__ float hi_(ull v) { return __uint_as_float((unsigned)(v >> 32)); }

__device__ __forceinline__ float sigm(float x) {
    float e = __expf(-x);
    float r;
    asm("rcp.approx.f32 %0, %1;" : "=f"(r) : "f"(1.0f + e));
    return r;
}

__global__ __launch_bounds__(128) void lstm_kernel(const int* __restrict__ tokens,
                                                   float* __restrict__ out)
{
    __shared__ float2 sH[4][8][HID];   // duplicated (h,h) per warp

    const int lane = threadIdx.x & 31;
    const int w    = threadIdx.x >> 5;
    const int b0   = (blockIdx.x * 4 + w) * 8;

    const int u1 = lane;
    const int u2 = lane + 32;          // may be >= HID (padded slot)
    const bool live2 = (u2 < HID);

    float c1[8], c2[8], h1[8], h2s[8];
    #pragma unroll
    for (int b = 0; b < 8; b++) { c1[b] = c2[b] = h1[b] = h2s[b] = 0.f; }

    #pragma unroll
    for (int b = 0; b < 8; b++) {
        sH[w][b][u1] = make_float2(0.f, 0.f);
        if (live2) sH[w][b][u2] = make_float2(0.f, 0.f);
    }
    __syncwarp();

    int tk[8];
    #pragma unroll
    for (int b = 0; b < 8; b++) tk[b] = __ldg(&tokens[(b0 + b) * TLEN]);

    const float4* __restrict__ Wp = gWk;
    const float4* __restrict__ Xp = gXT;

    for (int t = 0; t < TLEN; ++t) {
        // prefetch next step's tokens
        const int t2 = (t + 1 < TLEN) ? t + 1 : t;
        int tkn[8];
        #pragma unroll
        for (int b = 0; b < 8; b++) tkn[b] = __ldg(&tokens[(b0 + b) * TLEN + t2]);

        // init accumulators from gate-init table (token-indexed)
        ull a1if[8], a1go[8], a2if[8], a2go[8];
        #pragma unroll
        for (int b = 0; b < 8; b++) {
            float4 x0 = __ldg(&Xp[tk[b] * HP + u1]);
            float4 x1 = __ldg(&Xp[tk[b] * HP + u2]);
            a1if[b] = pk2(x0.x, x0.y);  a1go[b] = pk2(x0.z, x0.w);
            a2if[b] = pk2(x1.x, x1.y);  a2go[b] = pk2(x1.z, x1.w);
        }

        // recurrent matvec: gates += W_hh^T-slice * h
        #pragma unroll 5
        for (int k = 0; k < HID; k++) {
            float4 w0 = __ldg(&Wp[k * HP + u1]);
            float4 w1 = __ldg(&Wp[k * HP + u2]);
            ull w0if = pk2(w0.x, w0.y), w0go = pk2(w0.z, w0.w);
            ull w1if = pk2(w1.x, w1.y), w1go = pk2(w1.z, w1.w);
            #pragma unroll
            for (int b = 0; b < 8; b++) {
                ull hdup = *reinterpret_cast<const ull*>(&sH[w][b][k]);  // (h,h) broadcast
                a1if[b] = ffma2(w0if, hdup, a1if[b]);
                a1go[b] = ffma2(w0go, hdup, a1go[b]);
                a2if[b] = ffma2(w1if, hdup, a2if[b]);
                a2go[b] = ffma2(w1go, hdup, a2go[b]);
            }
        }

        __syncwarp();   // all lanes done reading sH for this step

        #pragma unroll
        for (int b = 0; b < 8; b++) {
            const bool live = (tk[b] != 0);
            {   // unit u1
                float gi = lo_(a1if[b]), gf = hi_(a1if[b]);
                float gg = lo_(a1go[b]), go = hi_(a1go[b]);
                float i = sigm(gi), f = sigm(gf), o = sigm(go);
                float g = 2.f * sigm(2.f * gg) - 1.f;        // tanh
                float cn = f * c1[b] + i * g;
                float hn = o * (2.f * sigm(2.f * cn) - 1.f);
                if (live) { c1[b] = cn; h1[b] = hn; }
                sH[w][b][u1] = make_float2(h1[b], h1[b]);
            }
            if (live2) {   // unit u2
                float gi = lo_(a2if[b]), gf = hi_(a2if[b]);
                float gg = lo_(a2go[b]), go = hi_(a2go[b]);
                float i = sigm(gi), f = sigm(gf), o = sigm(go);
                float g = 2.f * sigm(2.f * gg) - 1.f;
                float cn = f * c2[b] + i * g;
                float hn = o * (2.f * sigm(2.f * cn) - 1.f);
                if (live) { c2[b] = cn; h2s[b] = hn; }
                sH[w][b][u2] = make_float2(h2s[b], h2s[b]);
            }
        }
        __syncwarp();   // stores visible before next step's reads

        #pragma unroll
        for (int b = 0; b < 8; b++) tk[b] = tkn[b];
    }

    // collapsed MLP head: out = sigmoid(c0 + q . h_final)
    if (lane < 8) {
        const int b = lane;
        float s = gc0;
        #pragma unroll 10
        for (int k = 0; k < HID; k++) s += gq[k] * sH[w][b][k].x;
        out[b0 + b] = sigm(s);
    }
}

// ---------------------------------------------------------------------------
extern "C" void kernel_launch(void* const* d_in, const int* in_sizes, int n_in,
                              void* d_out, int out_size)
{
    const int*   tokens = (const int*)  d_in[0];
    const float* emb    = (const float*)d_in[1];
    const float* W_ih   = (const float*)d_in[2];
    const float* W_hh   = (const float*)d_in[3];
    const float* b_ih   = (const float*)d_in[4];
    const float* b_hh   = (const float*)d_in[5];
    const float* W1     = (const float*)d_in[6];
    const float* b1     = (const float*)d_in[7];
    const float* W2     = (const float*)d_in[8];
    const float* b2     = (const float*)d_in[9];
    float* out = (float*)d_out;

    prep_kernel<<<1, 256>>>(emb, W_ih, W_hh, b_ih, b_hh, W1, b1, W2, b2);
    lstm_kernel<<<NBATCH / 32, 128>>>(tokens, out);
}